// round 8
// baseline (speedup 1.0000x reference)
#include <cuda_runtime.h>
#include <cstdint>

// ============================================================================
// out[4096,1000] = core[4096,4096] @ weights[1000,4096]^T   (fp32)
//
// R8 vs R7 (182us):
//  - GEMM super-phases: 2 kt tiles per barrier/wait (stage pairs {0,1},{2,3},
//    one commit group per pair) -> 64 sync events instead of 128, cross-phase
//    ks=0 prefetch kept (wait_group 0 retires the next pair's group between
//    the 7th and 8th MMA block).
//  - pack kernels fused into one launch, 4 kt-chunks per thread (16
//    independent LDGs) to lift the pack off its latency plateau.
// ============================================================================

#define MDIM 4096
#define NDIM 1000
#define KDIM 4096

#define BM 256
#define BN 128
#define BK 32
#define KTILES (KDIM / BK)            // 128
#define STAGES 4
#define THREADS 256

#define A_TILE_BYTES (BM * BK * 4)    // 32768
#define B_TILE_BYTES (BN * BK * 4)    // 16384
#define STAGE_BYTES  (A_TILE_BYTES + B_TILE_BYTES)   // 49152
#define SMEM_BYTES   (STAGES * STAGE_BYTES)          // 196608

// packed scratch: A' = [16 mtiles][128 kt][2048 x 16B], B' = [8 ntiles][128 kt][2048 x 8B]
__device__ uint4 g_Ap[16 * 128 * 2048];   // 64 MB
__device__ uint2 g_Bp[8 * 128 * 2048];    // 16 MB

// ---------------------------------------------------------------------------
__device__ __forceinline__ uint32_t smem_u32(const void* p) {
    uint32_t a;
    asm("{ .reg .u64 t; cvta.to.shared.u64 t, %1; cvt.u32.u64 %0, t; }" : "=r"(a) : "l"(p));
    return a;
}

__device__ __forceinline__ void cp16(uint32_t dst, const void* src) {
    asm volatile("cp.async.cg.shared.global [%0], [%1], 16;"
                 :: "r"(dst), "l"(src) : "memory");
}
#define CP_COMMIT() asm volatile("cp.async.commit_group;" ::: "memory")
#define CP_WAIT0()  asm volatile("cp.async.wait_group 0;"  ::: "memory")
#define CP_WAIT1()  asm volatile("cp.async.wait_group 1;"  ::: "memory")

__device__ __forceinline__ uint32_t f2tf(float f) {
    uint32_t r;
    asm("cvt.rna.tf32.f32 %0, %1;" : "=r"(r) : "f"(f));
    return r;
}

__device__ __forceinline__ void mma_tf32(float c[4],
                                         const uint32_t a[4], const uint32_t b[2]) {
    asm volatile(
        "mma.sync.aligned.m16n8k8.row.col.f32.tf32.tf32.f32 "
        "{%0,%1,%2,%3}, {%4,%5,%6,%7}, {%8,%9}, {%0,%1,%2,%3};"
        : "+f"(c[0]), "+f"(c[1]), "+f"(c[2]), "+f"(c[3])
        : "r"(a[0]), "r"(a[1]), "r"(a[2]), "r"(a[3]), "r"(b[0]), "r"(b[1]));
}

// ---------------------------------------------------------------------------
// Fused pack kernel. Fragment-major layouts identical to R7:
//   A chunk ((wm*4+t)*4+ks)*32+lane -> 16B quad {A[r,c],A[r+8,c],A[r,c+4],A[r+8,c+4]}
//   B chunk ((wn*8+u)*4+ks)*32+lane -> 8B pair {B[n,c],B[n,c+4]}, n>=1000 zeroed
// Each thread handles 4 consecutive kt (16 / 8 independent LDGs).
// Blocks [0,4096): A.  Blocks [4096,6144): B.
// ---------------------------------------------------------------------------
__global__ void __launch_bounds__(256) pack_ab_kernel(const float* __restrict__ A,
                                                      const float* __restrict__ B) {
    const uint32_t bid = blockIdx.x;
    const uint32_t tidl = threadIdx.x;
    if (bid < 4096) {
        const uint32_t idx = bid * 256u + tidl;        // [0, 2^20)
        const uint32_t mtile = idx >> 16;              // 16 mtiles
        const uint32_t ktg   = (idx >> 11) & 31u;      // 32 kt-groups of 4
        const uint32_t chunk = idx & 2047u;
        const uint32_t lane  = chunk & 31u;
        const uint32_t blk   = chunk >> 5;
        const uint32_t ks    = blk & 3u;
        const uint32_t t     = (blk >> 2) & 3u;
        const uint32_t wm    = blk >> 4;
        const uint32_t r = mtile * 256 + wm * 64 + t * 16 + (lane >> 2);
        const float* rowp = A + (size_t)r * KDIM;
        #pragma unroll
        for (int j = 0; j < 4; j++) {
            const uint32_t kt = ktg * 4 + j;
            const uint32_t c  = kt * 32 + ks * 8 + (lane & 3);
            const float* p = rowp + c;
            uint4 v;
            v.x = f2tf(p[0]);
            v.y = f2tf(p[(size_t)8 * KDIM]);
            v.z = f2tf(p[4]);
            v.w = f2tf(p[(size_t)8 * KDIM + 4]);
            g_Ap[(size_t)(mtile * 128 + kt) * 2048 + chunk] = v;
        }
    } else {
        const uint32_t idx = (bid - 4096u) * 256u + tidl;  // [0, 2^19)
        const uint32_t ntile = idx >> 16;              // 8 ntiles
        const uint32_t ktg   = (idx >> 11) & 31u;
        const uint32_t chunk = idx & 2047u;
        const uint32_t lane  = chunk & 31u;
        const uint32_t blk   = chunk >> 5;
        const uint32_t ks    = blk & 3u;
        const uint32_t u     = (blk >> 2) & 7u;
        const uint32_t wn    = blk >> 5;
        const uint32_t n = ntile * 128 + wn * 64 + u * 8 + (lane >> 2);
        const float* rowp = B + (size_t)n * KDIM;
        #pragma unroll
        for (int j = 0; j < 4; j++) {
            const uint32_t kt = ktg * 4 + j;
            const uint32_t c  = kt * 32 + ks * 8 + (lane & 3);
            uint2 v = make_uint2(0u, 0u);
            if (n < NDIM) {
                const float* p = rowp + c;
                v.x = f2tf(p[0]);
                v.y = f2tf(p[4]);
            }
            g_Bp[(size_t)(ntile * 128 + kt) * 2048 + chunk] = v;
        }
    }
}

// ---------------------------------------------------------------------------
__global__ void __launch_bounds__(THREADS, 1)
tol_gemm_tf32(float* __restrict__ C) {         // [4096, 1000]
    extern __shared__ char smem[];
    const int tid  = threadIdx.x;
    const int wid  = tid >> 5;
    const int lane = tid & 31;

    const int mtile = blockIdx.y;
    const int ntile = blockIdx.x;
    const int m0 = mtile * BM;
    const int n0 = ntile * BN;

    const int warp_m = wid >> 1;     // 0..3
    const int warp_n = wid & 1;      // 0..1

    const uint32_t sb = smem_u32(smem);

#define ISSUE_STAGE(kt_, s_) do {                                                \
        const uint32_t soff = (uint32_t)(s_) * STAGE_BYTES;                      \
        const uint4* asrc = g_Ap + ((size_t)(mtile * KTILES + (kt_))) * 2048;    \
        const uint2* bsrc = g_Bp + ((size_t)(ntile * KTILES + (kt_))) * 2048;    \
        _Pragma("unroll")                                                        \
        for (int i = 0; i < 8; i++)                                              \
            cp16(sb + soff + (uint32_t)(tid + i * 256) * 16,                     \
                 asrc + tid + i * 256);                                          \
        _Pragma("unroll")                                                        \
        for (int i = 0; i < 4; i++)                                              \
            cp16(sb + soff + A_TILE_BYTES + (uint32_t)(tid + i * 256) * 16,      \
                 bsrc + (tid + i * 256) * 2);                                    \
    } while (0)

    float acc[4][8][4];
    #pragma unroll
    for (int t = 0; t < 4; t++)
        #pragma unroll
        for (int u = 0; u < 8; u++)
            #pragma unroll
            for (int i = 0; i < 4; i++)
                acc[t][u][i] = 0.0f;

    // fragment double buffers
    uint32_t af[2][4][4];
    uint32_t bf[2][8][2];

#define LOAD_FRAG(buf, aS, bS, ksv) do {                                         \
        _Pragma("unroll")                                                        \
        for (int t = 0; t < 4; t++) {                                            \
            uint4 v = (aS)[((warp_m * 4 + t) * 4 + (ksv)) * 32 + lane];          \
            af[buf][t][0] = v.x; af[buf][t][1] = v.y;                            \
            af[buf][t][2] = v.z; af[buf][t][3] = v.w;                            \
        }                                                                        \
        _Pragma("unroll")                                                        \
        for (int u = 0; u < 8; u++) {                                            \
            uint2 w = (bS)[((warp_n * 8 + u) * 4 + (ksv)) * 32 + lane];          \
            bf[buf][u][0] = w.x; bf[buf][u][1] = w.y;                            \
        }                                                                        \
    } while (0)

#define MMA_ALL(buf) do {                                                        \
        _Pragma("unroll")                                                        \
        for (int t = 0; t < 4; t++)                                              \
            _Pragma("unroll")                                                    \
            for (int u = 0; u < 8; u++)                                          \
                mma_tf32(acc[t][u], af[buf][t], bf[buf][u]);                     \
    } while (0)

#define STAGE_A(s_) reinterpret_cast<const uint4*>(smem + (s_) * STAGE_BYTES)
#define STAGE_B(s_) reinterpret_cast<const uint2*>(smem + (s_) * STAGE_BYTES + A_TILE_BYTES)

    // prologue: pair0 = {kt0,kt1} (group G0), pair1 = {kt2,kt3} (group G1)
    ISSUE_STAGE(0, 0); ISSUE_STAGE(1, 1); CP_COMMIT();
    ISSUE_STAGE(2, 2); ISSUE_STAGE(3, 3); CP_COMMIT();
    CP_WAIT1();
    __syncthreads();
    LOAD_FRAG(0, STAGE_A(0), STAGE_B(0), 0);   // frag(kt0, ks0)

    // One super-phase: consumes pair P (stages 2P, 2P+1 = data kt_, kt_+1).
    // Entry: buf0 = frag(kt_, ks0). Refill (for phase p+1's pair) targets pair
    // 1-P, which was consumed last phase; the barrier orders those reads before
    // these writes. wait_group 0 before the final MMA block retires the group
    // for the NEXT pair, making the cross-phase ks=0 prefetch safe.
#define SUPER(P, kt_) do {                                                       \
        __syncthreads();                                                         \
        if ((kt_) >= 2 && (kt_) + 2 < KTILES) {                                  \
            ISSUE_STAGE((kt_) + 2, 2 * (1 - (P)));                               \
            ISSUE_STAGE((kt_) + 3, 2 * (1 - (P)) + 1);                           \
            CP_COMMIT();                                                         \
        }                                                                        \
        const uint4* a0 = STAGE_A(2 * (P));                                      \
        const uint2* b0 = STAGE_B(2 * (P));                                      \
        const uint4* a1 = STAGE_A(2 * (P) + 1);                                  \
        const uint2* b1 = STAGE_B(2 * (P) + 1);                                  \
        LOAD_FRAG(1, a0, b0, 1);  MMA_ALL(0);                                    \
        LOAD_FRAG(0, a0, b0, 2);  MMA_ALL(1);                                    \
        LOAD_FRAG(1, a0, b0, 3);  MMA_ALL(0);                                    \
        LOAD_FRAG(0, a1, b1, 0);  MMA_ALL(1);                                    \
        LOAD_FRAG(1, a1, b1, 1);  MMA_ALL(0);                                    \
        LOAD_FRAG(0, a1, b1, 2);  MMA_ALL(1);                                    \
        LOAD_FRAG(1, a1, b1, 3);  MMA_ALL(0);                                    \
        if ((kt_) + 2 < KTILES) {                                                \
            CP_WAIT0();                                                          \
            const uint4* an = STAGE_A(2 * (1 - (P)));                            \
            const uint2* bn = STAGE_B(2 * (1 - (P)));                            \
            LOAD_FRAG(0, an, bn, 0);                                             \
        }                                                                        \
        MMA_ALL(1);                                                              \
    } while (0)

    for (int kt = 0; kt < KTILES; kt += 4) {
        SUPER(0, kt);
        SUPER(1, kt + 2);
    }

    // ---- epilogue: each warp writes its 64x64 region, guard N edge ----
    #pragma unroll
    for (int t = 0; t < 4; t++) {
        const int gr = m0 + warp_m * 64 + t * 16 + (lane >> 2);
        #pragma unroll
        for (int u = 0; u < 8; u++) {
            const int gc = n0 + warp_n * 64 + u * 8 + (lane & 3) * 2;
            if (gc < NDIM) {   // NDIM even; float2 never straddles the edge
                float2 v0 = make_float2(acc[t][u][0], acc[t][u][1]);
                float2 v1 = make_float2(acc[t][u][2], acc[t][u][3]);
                *reinterpret_cast<float2*>(C + (size_t)gr * NDIM + gc) = v0;
                *reinterpret_cast<float2*>(C + (size_t)(gr + 8) * NDIM + gc) = v1;
            }
        }
    }
}

// ---------------------------------------------------------------------------
extern "C" void kernel_launch(void* const* d_in, const int* in_sizes, int n_in,
                              void* d_out, int out_size) {
    const float* core = (const float*)d_in[0];   // [4096, 16,16,16] = [4096,4096]
    const float* wts  = (const float*)d_in[1];   // [1000, 4096]
    float* out = (float*)d_out;                  // [4096, 1000]

    // fused pack prepass (same stream -> ordered before GEMM)
    pack_ab_kernel<<<6144, 256>>>(core, wts);

    cudaFuncSetAttribute(tol_gemm_tf32,
                         cudaFuncAttributeMaxDynamicSharedMemorySize, SMEM_BYTES);

    dim3 grid(8, 16, 1);   // 128 CTAs = 1 clean wave
    tol_gemm_tf32<<<grid, THREADS, SMEM_BYTES>>>(out);
}

// round 9
// speedup vs baseline: 1.0052x; 1.0052x over previous
#include <cuda_runtime.h>
#include <cstdint>

// ============================================================================
// out[4096,1000] = core[4096,4096] @ weights[1000,4096]^T   (fp32)
//
// R9 vs R8: super-phases (1 barrier per 2 kt) kept, but with R7's per-kt
// commit groups and lag discipline. Phase(kt,kt+1): entry wait_group 0
// (drains G(kt+1), a full phase old) + barrier; refill G(kt+2),G(kt+3) right
// after the barrier into the stages consumed last phase; cross-phase ks0
// prefetch behind wait_group 1 (drains exactly G(kt+2), leaves G(kt+3)).
// This removes R8's mid-phase full-drain stall. Fused pack unchanged.
// ============================================================================

#define MDIM 4096
#define NDIM 1000
#define KDIM 4096

#define BM 256
#define BN 128
#define BK 32
#define KTILES (KDIM / BK)            // 128
#define STAGES 4
#define THREADS 256

#define A_TILE_BYTES (BM * BK * 4)    // 32768
#define B_TILE_BYTES (BN * BK * 4)    // 16384
#define STAGE_BYTES  (A_TILE_BYTES + B_TILE_BYTES)   // 49152
#define SMEM_BYTES   (STAGES * STAGE_BYTES)          // 196608

// packed scratch: A' = [16 mtiles][128 kt][2048 x 16B], B' = [8 ntiles][128 kt][2048 x 8B]
__device__ uint4 g_Ap[16 * 128 * 2048];   // 64 MB
__device__ uint2 g_Bp[8 * 128 * 2048];    // 16 MB

// ---------------------------------------------------------------------------
__device__ __forceinline__ uint32_t smem_u32(const void* p) {
    uint32_t a;
    asm("{ .reg .u64 t; cvta.to.shared.u64 t, %1; cvt.u32.u64 %0, t; }" : "=r"(a) : "l"(p));
    return a;
}

__device__ __forceinline__ void cp16(uint32_t dst, const void* src) {
    asm volatile("cp.async.cg.shared.global [%0], [%1], 16;"
                 :: "r"(dst), "l"(src) : "memory");
}
#define CP_COMMIT() asm volatile("cp.async.commit_group;" ::: "memory")
#define CP_WAIT0()  asm volatile("cp.async.wait_group 0;"  ::: "memory")
#define CP_WAIT1()  asm volatile("cp.async.wait_group 1;"  ::: "memory")
#define CP_WAIT2()  asm volatile("cp.async.wait_group 2;"  ::: "memory")

__device__ __forceinline__ uint32_t f2tf(float f) {
    uint32_t r;
    asm("cvt.rna.tf32.f32 %0, %1;" : "=r"(r) : "f"(f));
    return r;
}

__device__ __forceinline__ void mma_tf32(float c[4],
                                         const uint32_t a[4], const uint32_t b[2]) {
    asm volatile(
        "mma.sync.aligned.m16n8k8.row.col.f32.tf32.tf32.f32 "
        "{%0,%1,%2,%3}, {%4,%5,%6,%7}, {%8,%9}, {%0,%1,%2,%3};"
        : "+f"(c[0]), "+f"(c[1]), "+f"(c[2]), "+f"(c[3])
        : "r"(a[0]), "r"(a[1]), "r"(a[2]), "r"(a[3]), "r"(b[0]), "r"(b[1]));
}

// ---------------------------------------------------------------------------
// Fused pack kernel (same as R8). Fragment-major layouts:
//   A chunk ((wm*4+t)*4+ks)*32+lane -> 16B quad {A[r,c],A[r+8,c],A[r,c+4],A[r+8,c+4]}
//   B chunk ((wn*8+u)*4+ks)*32+lane -> 8B pair {B[n,c],B[n,c+4]}, n>=1000 zeroed
// ---------------------------------------------------------------------------
__global__ void __launch_bounds__(256) pack_ab_kernel(const float* __restrict__ A,
                                                      const float* __restrict__ B) {
    const uint32_t bid = blockIdx.x;
    const uint32_t tidl = threadIdx.x;
    if (bid < 4096) {
        const uint32_t idx = bid * 256u + tidl;        // [0, 2^20)
        const uint32_t mtile = idx >> 16;
        const uint32_t ktg   = (idx >> 11) & 31u;
        const uint32_t chunk = idx & 2047u;
        const uint32_t lane  = chunk & 31u;
        const uint32_t blk   = chunk >> 5;
        const uint32_t ks    = blk & 3u;
        const uint32_t t     = (blk >> 2) & 3u;
        const uint32_t wm    = blk >> 4;
        const uint32_t r = mtile * 256 + wm * 64 + t * 16 + (lane >> 2);
        const float* rowp = A + (size_t)r * KDIM;
        #pragma unroll
        for (int j = 0; j < 4; j++) {
            const uint32_t kt = ktg * 4 + j;
            const uint32_t c  = kt * 32 + ks * 8 + (lane & 3);
            const float* p = rowp + c;
            uint4 v;
            v.x = f2tf(p[0]);
            v.y = f2tf(p[(size_t)8 * KDIM]);
            v.z = f2tf(p[4]);
            v.w = f2tf(p[(size_t)8 * KDIM + 4]);
            g_Ap[(size_t)(mtile * 128 + kt) * 2048 + chunk] = v;
        }
    } else {
        const uint32_t idx = (bid - 4096u) * 256u + tidl;  // [0, 2^19)
        const uint32_t ntile = idx >> 16;
        const uint32_t ktg   = (idx >> 11) & 31u;
        const uint32_t chunk = idx & 2047u;
        const uint32_t lane  = chunk & 31u;
        const uint32_t blk   = chunk >> 5;
        const uint32_t ks    = blk & 3u;
        const uint32_t u     = (blk >> 2) & 7u;
        const uint32_t wn    = blk >> 5;
        const uint32_t n = ntile * 128 + wn * 64 + u * 8 + (lane >> 2);
        const float* rowp = B + (size_t)n * KDIM;
        #pragma unroll
        for (int j = 0; j < 4; j++) {
            const uint32_t kt = ktg * 4 + j;
            const uint32_t c  = kt * 32 + ks * 8 + (lane & 3);
            uint2 v = make_uint2(0u, 0u);
            if (n < NDIM) {
                const float* p = rowp + c;
                v.x = f2tf(p[0]);
                v.y = f2tf(p[4]);
            }
            g_Bp[(size_t)(ntile * 128 + kt) * 2048 + chunk] = v;
        }
    }
}

// ---------------------------------------------------------------------------
__global__ void __launch_bounds__(THREADS, 1)
tol_gemm_tf32(float* __restrict__ C) {         // [4096, 1000]
    extern __shared__ char smem[];
    const int tid  = threadIdx.x;
    const int wid  = tid >> 5;
    const int lane = tid & 31;

    const int mtile = blockIdx.y;
    const int ntile = blockIdx.x;
    const int m0 = mtile * BM;
    const int n0 = ntile * BN;

    const int warp_m = wid >> 1;     // 0..3
    const int warp_n = wid & 1;      // 0..1

    const uint32_t sb = smem_u32(smem);

#define ISSUE_STAGE(kt_, s_) do {                                                \
        const uint32_t soff = (uint32_t)(s_) * STAGE_BYTES;                      \
        const uint4* asrc = g_Ap + ((size_t)(mtile * KTILES + (kt_))) * 2048;    \
        const uint2* bsrc = g_Bp + ((size_t)(ntile * KTILES + (kt_))) * 2048;    \
        _Pragma("unroll")                                                        \
        for (int i = 0; i < 8; i++)                                              \
            cp16(sb + soff + (uint32_t)(tid + i * 256) * 16,                     \
                 asrc + tid + i * 256);                                          \
        _Pragma("unroll")                                                        \
        for (int i = 0; i < 4; i++)                                              \
            cp16(sb + soff + A_TILE_BYTES + (uint32_t)(tid + i * 256) * 16,      \
                 bsrc + (tid + i * 256) * 2);                                    \
    } while (0)

    float acc[4][8][4];
    #pragma unroll
    for (int t = 0; t < 4; t++)
        #pragma unroll
        for (int u = 0; u < 8; u++)
            #pragma unroll
            for (int i = 0; i < 4; i++)
                acc[t][u][i] = 0.0f;

    // fragment double buffers
    uint32_t af[2][4][4];
    uint32_t bf[2][8][2];

#define LOAD_FRAG(buf, aS, bS, ksv) do {                                         \
        _Pragma("unroll")                                                        \
        for (int t = 0; t < 4; t++) {                                            \
            uint4 v = (aS)[((warp_m * 4 + t) * 4 + (ksv)) * 32 + lane];          \
            af[buf][t][0] = v.x; af[buf][t][1] = v.y;                            \
            af[buf][t][2] = v.z; af[buf][t][3] = v.w;                            \
        }                                                                        \
        _Pragma("unroll")                                                        \
        for (int u = 0; u < 8; u++) {                                            \
            uint2 w = (bS)[((warp_n * 8 + u) * 4 + (ksv)) * 32 + lane];          \
            bf[buf][u][0] = w.x; bf[buf][u][1] = w.y;                            \
        }                                                                        \
    } while (0)

#define MMA_ALL(buf) do {                                                        \
        _Pragma("unroll")                                                        \
        for (int t = 0; t < 4; t++)                                              \
            _Pragma("unroll")                                                    \
            for (int u = 0; u < 8; u++)                                          \
                mma_tf32(acc[t][u], af[buf][t], bf[buf][u]);                     \
    } while (0)

#define STAGE_A(s_) reinterpret_cast<const uint4*>(smem + (s_) * STAGE_BYTES)
#define STAGE_B(s_) reinterpret_cast<const uint2*>(smem + (s_) * STAGE_BYTES + A_TILE_BYTES)

    // prologue: per-kt groups G0..G3 into stages 0..3
    ISSUE_STAGE(0, 0); CP_COMMIT();
    ISSUE_STAGE(1, 1); CP_COMMIT();
    ISSUE_STAGE(2, 2); CP_COMMIT();
    ISSUE_STAGE(3, 3); CP_COMMIT();
    CP_WAIT2();                       // drain G0,G1 (leave G2,G3 in flight)
    __syncthreads();
    LOAD_FRAG(0, STAGE_A(0), STAGE_B(0), 0);   // frag(kt0, ks0)

    // Super-phase handling (kt_, kt_+1) at compile-time stage pair P
    // (P=0 -> stages {0,1}, P=1 -> {2,3}). Entry: buf0 = frag(kt_, ks0);
    // all groups up to G(kt_+1) drained before the barrier. Refills target
    // the pair consumed LAST phase. Prefetch of frag(kt_+2, ks0) sits behind
    // wait_group 1, which drains exactly G(kt_+2) and leaves G(kt_+3).
#define PHASE2(P, kt_) do {                                                      \
        if ((kt_) > 0) {                                                         \
            CP_WAIT0();               /* drains G(kt_+1), a full phase old */    \
            __syncthreads();                                                     \
        }                                                                        \
        if ((kt_) >= 2 && (kt_) + 2 < KTILES) {                                  \
            ISSUE_STAGE((kt_) + 2, 2 * (1 - (P)));     CP_COMMIT();              \
            ISSUE_STAGE((kt_) + 3, 2 * (1 - (P)) + 1); CP_COMMIT();              \
        }                                                                        \
        const uint4* a0 = STAGE_A(2 * (P));                                      \
        const uint2* b0 = STAGE_B(2 * (P));                                      \
        const uint4* a1 = STAGE_A(2 * (P) + 1);                                  \
        const uint2* b1 = STAGE_B(2 * (P) + 1);                                  \
        LOAD_FRAG(1, a0, b0, 1);  MMA_ALL(0);                                    \
        LOAD_FRAG(0, a0, b0, 2);  MMA_ALL(1);                                    \
        LOAD_FRAG(1, a0, b0, 3);  MMA_ALL(0);                                    \
        LOAD_FRAG(0, a1, b1, 0);  MMA_ALL(1);                                    \
        LOAD_FRAG(1, a1, b1, 1);  MMA_ALL(0);                                    \
        LOAD_FRAG(0, a1, b1, 2);  MMA_ALL(1);                                    \
        LOAD_FRAG(1, a1, b1, 3);  MMA_ALL(0);                                    \
        if ((kt_) + 2 < KTILES) {                                                \
            CP_WAIT1();               /* drains G(kt_+2), leaves G(kt_+3) */     \
            LOAD_FRAG(0, STAGE_A(2 * (1 - (P))), STAGE_B(2 * (1 - (P))), 0);     \
        }                                                                        \
        MMA_ALL(1);                                                              \
    } while (0)

    for (int kt = 0; kt < KTILES; kt += 4) {
        PHASE2(0, kt);
        PHASE2(1, kt + 2);
    }

    // ---- epilogue: each warp writes its 64x64 region, guard N edge ----
    #pragma unroll
    for (int t = 0; t < 4; t++) {
        const int gr = m0 + warp_m * 64 + t * 16 + (lane >> 2);
        #pragma unroll
        for (int u = 0; u < 8; u++) {
            const int gc = n0 + warp_n * 64 + u * 8 + (lane & 3) * 2;
            if (gc < NDIM) {   // NDIM even; float2 never straddles the edge
                float2 v0 = make_float2(acc[t][u][0], acc[t][u][1]);
                float2 v1 = make_float2(acc[t][u][2], acc[t][u][3]);
                *reinterpret_cast<float2*>(C + (size_t)gr * NDIM + gc) = v0;
                *reinterpret_cast<float2*>(C + (size_t)(gr + 8) * NDIM + gc) = v1;
            }
        }
    }
}

// ---------------------------------------------------------------------------
extern "C" void kernel_launch(void* const* d_in, const int* in_sizes, int n_in,
                              void* d_out, int out_size) {
    const float* core = (const float*)d_in[0];   // [4096, 16,16,16] = [4096,4096]
    const float* wts  = (const float*)d_in[1];   // [1000, 4096]
    float* out = (float*)d_out;                  // [4096, 1000]

    // fused pack prepass (same stream -> ordered before GEMM)
    pack_ab_kernel<<<6144, 256>>>(core, wts);

    cudaFuncSetAttribute(tol_gemm_tf32,
                         cudaFuncAttributeMaxDynamicSharedMemorySize, SMEM_BYTES);

    dim3 grid(8, 16, 1);   // 128 CTAs = 1 clean wave
    tol_gemm_tf32<<<grid, THREADS, SMEM_BYTES>>>(out);
}